// round 12
// baseline (speedup 1.0000x reference)
#include <cuda_runtime.h>
#include <math.h>

#define NO 2048
#define NI 16
#define NF 4
#define ND 128
#define NN 8
#define NT 256

typedef unsigned long long u64;

// smem floats
#define OFF_FAC  0        // 8192
#define OFF_FEAT 8192     // 2048
#define OFF_SCR  10240    // 6144 (ctr 8x512 / ph1 h / ph4 scratch)
#define OFF_B1   16384
#define OFF_B2   16512
#define OFF_RED  16640    // 64
#define OFF_INT  16704    // 432 ints
#define SMEM_BYTES ((16704 + 432)*4)   // 68544 B -> 2 CTAs/SM, L1D ~94KB

#define GW_CF1 0
#define GW_CF2 16384
#define GW_F2F1 32768
#define GW_F2F2 40960
#define GW_F2I1 49152
#define GW_F2I2 57344
#define GW_I2I1 65536
#define GW_I2I2 73728
__device__ u64 g_w[81920];
__device__ float g_com_partial[NO];
__device__ unsigned g_counter = 0;

__device__ __forceinline__ float lrelu(float v){ return v >= 0.f ? v : 0.01f*v; }
__device__ __forceinline__ u64 packff(float lo, float hi){
    u64 d; asm("mov.b64 %0, {%1, %2};" : "=l"(d) : "f"(lo), "f"(hi)); return d; }
__device__ __forceinline__ u64 f2fma(u64 a, u64 b, u64 c){
    u64 d; asm("fma.rn.f32x2 %0, %1, %2, %3;" : "=l"(d) : "l"(a), "l"(b), "l"(c)); return d; }
__device__ __forceinline__ u64 f2mul(u64 a, u64 b){
    u64 d; asm("mul.rn.f32x2 %0, %1, %2;" : "=l"(d) : "l"(a), "l"(b)); return d; }
__device__ __forceinline__ float f2red(u64 v){
    float lo, hi; asm("mov.b64 {%0, %1}, %2;" : "=f"(lo), "=f"(hi) : "l"(v)); return lo + hi; }
__device__ __forceinline__ ulonglong2 ld2f(const float* pf){ return *(const ulonglong2*)pf; }
__device__ __forceinline__ ulonglong2 ldg2(const u64* p){ return *(const ulonglong2*)p; }

__global__ void pack_all(const float* __restrict__ s0, const float* __restrict__ s1,
                         const float* __restrict__ s2, const float* __restrict__ s3,
                         const float* __restrict__ s4, const float* __restrict__ s5,
                         const float* __restrict__ s6, const float* __restrict__ s7,
                         u64* __restrict__ dst){
    int idx = blockIdx.x*256 + threadIdx.x;
    if (idx >= 81920) return;
    const float* src; int base, cshift;
    if (idx < 16384){ src = s0; base = 0; cshift = 6; }
    else if (idx < 32768){ src = s1; base = 16384; cshift = 7; }
    else {
        int t = (idx - 32768) >> 13;
        src = (t==0)?s2:(t==1)?s3:(t==2)?s4:(t==3)?s5:(t==4)?s6:s7;
        base = 32768 + t*8192; cshift = 7;
    }
    int l = idx - base;
    int k2 = l >> cshift, d = l & ((1 << cshift) - 1);
    dst[idx] = packff(src[((2*k2) << cshift) + d], src[((2*k2+1) << cshift) + d]);
}

__device__ __forceinline__ void load_f(float* dst, const float* src, int n){
    for (int i = threadIdx.x; i < n; i += NT) dst[i] = src[i];
}

__global__ __launch_bounds__(NT, 2)
void mfgn_kernel(
    const int* __restrict__ outfit_items, const float* __restrict__ items_feature,
    const int* __restrict__ items_neighbor,
    const float* __restrict__ cf_b1, const float* __restrict__ cf_b2,
    const float* __restrict__ f2f_b1, const float* __restrict__ f2f_b2,
    const float* __restrict__ f2i_b1, const float* __restrict__ f2i_b2,
    const float* __restrict__ i2i_b1, const float* __restrict__ i2i_b2,
    const float* __restrict__ o2s_W,  const float* __restrict__ o2s_b,
    float* __restrict__ d_out)
{
    extern __shared__ float sm[];
    float* s_fac  = sm + OFF_FAC;
    float* s_feat = sm + OFF_FEAT;
    float* s_scr  = sm + OFF_SCR;
    float* s_b1   = sm + OFF_B1;
    float* s_b2   = sm + OFF_B2;
    float* s_red  = sm + OFF_RED;
    int*   s_items = (int*)(sm + OFF_INT);
    int*   s_nbr   = s_items + NI;
    int*   s_count = s_nbr + NI*NN;
    int*   s_cand  = s_count + NI;            // [8][16]
    float* s_cmask = (float*)(s_cand + 128);  // [8][16]
    int*   s_flag  = (int*)(s_cmask + 128);

    const int o = blockIdx.x, tid = threadIdx.x;
    const int w = tid >> 5, lane = tid & 31;
    const int d4 = lane*4;

    if (tid < NI)    s_items[tid] = outfit_items[o*NI + tid];
    if (tid < NI*NN) s_nbr[tid]   = items_neighbor[o*NI*NN + tid];
    load_f(s_feat, items_feature + (size_t)o*NI*ND, NI*ND);
    __syncthreads();
    if (tid < NI){
        int c = 0;
        #pragma unroll
        for (int s = 0; s < 8; s++) c += (s_items[s] == tid);
        s_count[tid] = c;
    }
    {   // dedup'd candidates with multiplicity; warp w -> step w
        const int i = s_items[w];
        int c = -1; bool v = false;
        if (i >= 0 && lane < NI + NN){
            c = (lane < NI) ? s_items[lane] : s_nbr[i*NN + (lane - NI)];
            v = (c != -1) && (c != i);
        }
        unsigned vb = __ballot_sync(0xffffffffu, v);
        unsigned mt = __match_any_sync(0xffffffffu, c) & vb;
        bool leader = v && ((mt & (0u - mt)) == (1u << lane));
        unsigned lb = __ballot_sync(0xffffffffu, leader);
        if (lane < 16){ s_cand[w*16 + lane] = 0; s_cmask[w*16 + lane] = 0.f; }
        __syncwarp();
        if (leader){
            int pos = __popc(lb & ((1u << lane) - 1));
            s_cand[w*16 + pos] = c;
            s_cmask[w*16 + pos] = (float)__popc(mt);
        }
    }

    // ===== Phase 1: creat_factors. warp w: items 2w,2w+1; loop f =====
    {
        const int i0 = 2*w, i1 = 2*w + 1;
        float* hrow = s_scr + w*256;
        for (int f = 0; f < NF; f++){
            const u64* W1 = g_w + GW_CF1 + f*4096;
            const u64* W2 = g_w + GW_CF2 + f*4096;
            u64 a[2][2] = {{0,0},{0,0}};
            #pragma unroll 4
            for (int q = 0; q < 32; q++){
                u64 w0 = W1[(2*q)*64 + lane*2],   w0b = W1[(2*q)*64 + lane*2 + 1];
                u64 w1 = W1[(2*q+1)*64 + lane*2], w1b = W1[(2*q+1)*64 + lane*2 + 1];
                ulonglong2 x0 = ld2f(&s_feat[i0*ND + 4*q]);
                ulonglong2 x1 = ld2f(&s_feat[i1*ND + 4*q]);
                a[0][0]=f2fma(x0.x,w0,a[0][0]);  a[0][0]=f2fma(x0.y,w1,a[0][0]);
                a[0][1]=f2fma(x0.x,w0b,a[0][1]); a[0][1]=f2fma(x0.y,w1b,a[0][1]);
                a[1][0]=f2fma(x1.x,w0,a[1][0]);  a[1][0]=f2fma(x1.y,w1,a[1][0]);
                a[1][1]=f2fma(x1.x,w0b,a[1][1]); a[1][1]=f2fma(x1.y,w1b,a[1][1]);
            }
            float b10 = cf_b1[f*64 + lane*2], b11 = cf_b1[f*64 + lane*2 + 1];
            hrow[0*128 + lane*2+0] = lrelu(f2red(a[0][0]) + b10);
            hrow[0*128 + lane*2+1] = lrelu(f2red(a[0][1]) + b11);
            hrow[1*128 + lane*2+0] = lrelu(f2red(a[1][0]) + b10);
            hrow[1*128 + lane*2+1] = lrelu(f2red(a[1][1]) + b11);
            __syncwarp();
            u64 c2[2][4] = {{0,0,0,0},{0,0,0,0}};
            #pragma unroll 4
            for (int q = 0; q < 16; q++){
                ulonglong2 wa0 = ldg2(&W2[(2*q)*ND + d4]),   wb0 = ldg2(&W2[(2*q)*ND + d4 + 2]);
                ulonglong2 wa1 = ldg2(&W2[(2*q+1)*ND + d4]), wb1 = ldg2(&W2[(2*q+1)*ND + d4 + 2]);
                ulonglong2 h0 = ld2f(&hrow[0*128 + 4*q]);
                ulonglong2 h1 = ld2f(&hrow[1*128 + 4*q]);
                c2[0][0]=f2fma(h0.x,wa0.x,c2[0][0]); c2[0][0]=f2fma(h0.y,wa1.x,c2[0][0]);
                c2[0][1]=f2fma(h0.x,wa0.y,c2[0][1]); c2[0][1]=f2fma(h0.y,wa1.y,c2[0][1]);
                c2[0][2]=f2fma(h0.x,wb0.x,c2[0][2]); c2[0][2]=f2fma(h0.y,wb1.x,c2[0][2]);
                c2[0][3]=f2fma(h0.x,wb0.y,c2[0][3]); c2[0][3]=f2fma(h0.y,wb1.y,c2[0][3]);
                c2[1][0]=f2fma(h1.x,wa0.x,c2[1][0]); c2[1][0]=f2fma(h1.y,wa1.x,c2[1][0]);
                c2[1][1]=f2fma(h1.x,wa0.y,c2[1][1]); c2[1][1]=f2fma(h1.y,wa1.y,c2[1][1]);
                c2[1][2]=f2fma(h1.x,wb0.x,c2[1][2]); c2[1][2]=f2fma(h1.y,wb1.x,c2[1][2]);
                c2[1][3]=f2fma(h1.x,wb0.y,c2[1][3]); c2[1][3]=f2fma(h1.y,wb1.y,c2[1][3]);
            }
            #pragma unroll
            for (int r = 0; r < 2; r++)
                #pragma unroll
                for (int j = 0; j < 4; j++)
                    s_fac[(2*w+r)*512 + f*ND + d4 + j] =
                        lrelu(f2red(c2[r][j]) + cf_b2[f*ND + d4 + j]);
            __syncwarp();
        }
    }
    __syncthreads();
    load_f(s_b1, f2f_b1, ND);
    load_f(s_b2, f2f_b2, ND);
    __syncthreads();

    // ===== Phase 2: inter_factors. h in registers, shuffle transpose =====
    {
        const u64* W1 = g_w + GW_F2F1;
        const u64* W2 = g_w + GW_F2F2;
        for (int step = 0; step < 8; step++){
            const int i = s_items[step];
            if (i < 0) continue;
            const float m0 = s_cmask[step*16 + 2*w], m1 = s_cmask[step*16 + 2*w + 1];
            if (m0 != 0.f){
                const int c0 = s_cand[step*16 + 2*w], c1 = s_cand[step*16 + 2*w + 1];
                const float* tb = s_fac + i*512;
                const float* e0 = s_fac + c0*512;
                const float* e1 = s_fac + c1*512;
                u64 a[2][4][4];
                #pragma unroll
                for (int c = 0; c < 2; c++)
                    #pragma unroll
                    for (int f = 0; f < 4; f++)
                        #pragma unroll
                        for (int j = 0; j < 4; j++) a[c][f][j] = 0;
                #pragma unroll 2
                for (int q = 0; q < 32; q++){
                    ulonglong2 wa0 = ldg2(&W1[(2*q)*ND + d4]),   wb0 = ldg2(&W1[(2*q)*ND + d4 + 2]);
                    ulonglong2 wa1 = ldg2(&W1[(2*q+1)*ND + d4]), wb1 = ldg2(&W1[(2*q+1)*ND + d4 + 2]);
                    #pragma unroll
                    for (int f = 0; f < 4; f++){
                        ulonglong2 t  = ld2f(&tb[f*ND + 4*q]);
                        ulonglong2 x0 = ld2f(&e0[f*ND + 4*q]);
                        ulonglong2 x1 = ld2f(&e1[f*ND + 4*q]);
                        u64 p0 = f2mul(t.x, x0.x), p1 = f2mul(t.y, x0.y);
                        a[0][f][0]=f2fma(p0,wa0.x,a[0][f][0]); a[0][f][0]=f2fma(p1,wa1.x,a[0][f][0]);
                        a[0][f][1]=f2fma(p0,wa0.y,a[0][f][1]); a[0][f][1]=f2fma(p1,wa1.y,a[0][f][1]);
                        a[0][f][2]=f2fma(p0,wb0.x,a[0][f][2]); a[0][f][2]=f2fma(p1,wb1.x,a[0][f][2]);
                        a[0][f][3]=f2fma(p0,wb0.y,a[0][f][3]); a[0][f][3]=f2fma(p1,wb1.y,a[0][f][3]);
                        u64 r0 = f2mul(t.x, x1.x), r1 = f2mul(t.y, x1.y);
                        a[1][f][0]=f2fma(r0,wa0.x,a[1][f][0]); a[1][f][0]=f2fma(r1,wa1.x,a[1][f][0]);
                        a[1][f][1]=f2fma(r0,wa0.y,a[1][f][1]); a[1][f][1]=f2fma(r1,wa1.y,a[1][f][1]);
                        a[1][f][2]=f2fma(r0,wb0.x,a[1][f][2]); a[1][f][2]=f2fma(r1,wb1.x,a[1][f][2]);
                        a[1][f][3]=f2fma(r0,wb0.y,a[1][f][3]); a[1][f][3]=f2fma(r1,wb1.y,a[1][f][3]);
                    }
                }
                // h in registers: lane holds dims 4*lane..+3 per row
                u64 h01[8], h23[8];
                #pragma unroll
                for (int c = 0; c < 2; c++)
                    #pragma unroll
                    for (int f = 0; f < 4; f++){
                        int r = c*4 + f;
                        float v0 = lrelu(f2red(a[c][f][0]) + s_b1[d4+0]);
                        float v1 = lrelu(f2red(a[c][f][1]) + s_b1[d4+1]);
                        float v2 = lrelu(f2red(a[c][f][2]) + s_b1[d4+2]);
                        float v3 = lrelu(f2red(a[c][f][3]) + s_b1[d4+3]);
                        h01[r] = packff(v0, v1);
                        h23[r] = packff(v2, v3);
                    }
                u64 b[2][4][4];
                #pragma unroll
                for (int c = 0; c < 2; c++)
                    #pragma unroll
                    for (int f = 0; f < 4; f++)
                        #pragma unroll
                        for (int j = 0; j < 4; j++) b[c][f][j] = 0;
                #pragma unroll 2
                for (int q = 0; q < 32; q++){
                    ulonglong2 wa0 = ldg2(&W2[(2*q)*ND + d4]),   wb0 = ldg2(&W2[(2*q)*ND + d4 + 2]);
                    ulonglong2 wa1 = ldg2(&W2[(2*q+1)*ND + d4]), wb1 = ldg2(&W2[(2*q+1)*ND + d4 + 2]);
                    #pragma unroll
                    for (int c = 0; c < 2; c++)
                        #pragma unroll
                        for (int f = 0; f < 4; f++){
                            int r = c*4 + f;
                            u64 hx = __shfl_sync(0xffffffffu, h01[r], q);
                            u64 hy = __shfl_sync(0xffffffffu, h23[r], q);
                            b[c][f][0]=f2fma(hx,wa0.x,b[c][f][0]); b[c][f][0]=f2fma(hy,wa1.x,b[c][f][0]);
                            b[c][f][1]=f2fma(hx,wa0.y,b[c][f][1]); b[c][f][1]=f2fma(hy,wa1.y,b[c][f][1]);
                            b[c][f][2]=f2fma(hx,wb0.x,b[c][f][2]); b[c][f][2]=f2fma(hy,wb1.x,b[c][f][2]);
                            b[c][f][3]=f2fma(hx,wb0.y,b[c][f][3]); b[c][f][3]=f2fma(hy,wb1.y,b[c][f][3]);
                        }
                }
                #pragma unroll
                for (int f = 0; f < 4; f++)
                    #pragma unroll
                    for (int j = 0; j < 4; j++){
                        float y0 = lrelu(f2red(b[0][f][j]) + s_b2[d4 + j]);
                        float y1 = lrelu(f2red(b[1][f][j]) + s_b2[d4 + j]);
                        s_scr[w*512 + f*ND + d4 + j] = m0*y0 + m1*y1;
                    }
            } else {
                #pragma unroll
                for (int f = 0; f < 4; f++)
                    #pragma unroll
                    for (int j = 0; j < 4; j++)
                        s_scr[w*512 + f*ND + d4 + j] = 0.f;
            }
            __syncthreads();
            #pragma unroll
            for (int rep = 0; rep < 2; rep++){
                int idx = tid + rep*256;
                float s = 0.f;
                #pragma unroll
                for (int pp = 0; pp < 8; pp++) s += s_scr[pp*512 + idx];
                s_fac[i*512 + idx] += s;
            }
            __syncthreads();
        }
    }

    // ===== com partial: warp w -> positions 2w, 2w+1 =====
    {
        float csum = 0.f;
        #pragma unroll
        for (int t2 = 0; t2 < 2; t2++){
            int pos = 2*w + t2;
            if (s_items[pos] != -1){
                const float* fp = s_fac + pos*512;
                #pragma unroll
                for (int aa = 0; aa < NF; aa++)
                    #pragma unroll
                    for (int bb = 0; bb < NF; bb++){
                        float pr = 0.f;
                        #pragma unroll
                        for (int k = 0; k < 4; k++)
                            pr += fp[aa*ND + lane + 32*k] * fp[bb*ND + lane + 32*k];
                        #pragma unroll
                        for (int off2 = 16; off2; off2 >>= 1)
                            pr += __shfl_xor_sync(0xffffffffu, pr, off2);
                        float gg = pr - (aa == bb ? 1.f : 0.f);
                        csum += gg*gg;
                    }
            }
        }
        if (lane == 0) s_red[w] = csum;
    }
    __syncthreads();
    load_f(s_b1, f2i_b1, ND);
    load_f(s_b2, f2i_b2, ND);
    __syncthreads();

    // ===== Phase 3: infer_items. warp w: items 2w,2w+1, h in registers =====
    {
        const u64* W1 = g_w + GW_F2I1;
        const u64* W2 = g_w + GW_F2I2;
        const int cn0 = s_count[2*w], cn1 = s_count[2*w+1];
        if (cn0 > 0 || cn1 > 0){
            u64 a[2][4][4];
            #pragma unroll
            for (int c = 0; c < 2; c++)
                #pragma unroll
                for (int f = 0; f < 4; f++)
                    #pragma unroll
                    for (int j = 0; j < 4; j++) a[c][f][j] = 0;
            #pragma unroll 2
            for (int q = 0; q < 32; q++){
                ulonglong2 wa0 = ldg2(&W1[(2*q)*ND + d4]),   wb0 = ldg2(&W1[(2*q)*ND + d4 + 2]);
                ulonglong2 wa1 = ldg2(&W1[(2*q+1)*ND + d4]), wb1 = ldg2(&W1[(2*q+1)*ND + d4 + 2]);
                #pragma unroll
                for (int c = 0; c < 2; c++)
                    #pragma unroll
                    for (int f = 0; f < 4; f++){
                        ulonglong2 x = ld2f(&s_fac[(2*w+c)*512 + f*ND + 4*q]);
                        a[c][f][0]=f2fma(x.x,wa0.x,a[c][f][0]); a[c][f][0]=f2fma(x.y,wa1.x,a[c][f][0]);
                        a[c][f][1]=f2fma(x.x,wa0.y,a[c][f][1]); a[c][f][1]=f2fma(x.y,wa1.y,a[c][f][1]);
                        a[c][f][2]=f2fma(x.x,wb0.x,a[c][f][2]); a[c][f][2]=f2fma(x.y,wb1.x,a[c][f][2]);
                        a[c][f][3]=f2fma(x.x,wb0.y,a[c][f][3]); a[c][f][3]=f2fma(x.y,wb1.y,a[c][f][3]);
                    }
            }
            u64 h01[8], h23[8];
            #pragma unroll
            for (int c = 0; c < 2; c++)
                #pragma unroll
                for (int f = 0; f < 4; f++){
                    int r = c*4 + f;
                    float v0 = lrelu(f2red(a[c][f][0]) + s_b1[d4+0]);
                    float v1 = lrelu(f2red(a[c][f][1]) + s_b1[d4+1]);
                    float v2 = lrelu(f2red(a[c][f][2]) + s_b1[d4+2]);
                    float v3 = lrelu(f2red(a[c][f][3]) + s_b1[d4+3]);
                    h01[r] = packff(v0, v1);
                    h23[r] = packff(v2, v3);
                }
            u64 b[2][4][4];
            #pragma unroll
            for (int c = 0; c < 2; c++)
                #pragma unroll
                for (int f = 0; f < 4; f++)
                    #pragma unroll
                    for (int j = 0; j < 4; j++) b[c][f][j] = 0;
            #pragma unroll 2
            for (int q = 0; q < 32; q++){
                ulonglong2 wa0 = ldg2(&W2[(2*q)*ND + d4]),   wb0 = ldg2(&W2[(2*q)*ND + d4 + 2]);
                ulonglong2 wa1 = ldg2(&W2[(2*q+1)*ND + d4]), wb1 = ldg2(&W2[(2*q+1)*ND + d4 + 2]);
                #pragma unroll
                for (int c = 0; c < 2; c++)
                    #pragma unroll
                    for (int f = 0; f < 4; f++){
                        int r = c*4 + f;
                        u64 hx = __shfl_sync(0xffffffffu, h01[r], q);
                        u64 hy = __shfl_sync(0xffffffffu, h23[r], q);
                        b[c][f][0]=f2fma(hx,wa0.x,b[c][f][0]); b[c][f][0]=f2fma(hy,wa1.x,b[c][f][0]);
                        b[c][f][1]=f2fma(hx,wa0.y,b[c][f][1]); b[c][f][1]=f2fma(hy,wa1.y,b[c][f][1]);
                        b[c][f][2]=f2fma(hx,wb0.x,b[c][f][2]); b[c][f][2]=f2fma(hy,wb1.x,b[c][f][2]);
                        b[c][f][3]=f2fma(hx,wb0.y,b[c][f][3]); b[c][f][3]=f2fma(hy,wb1.y,b[c][f][3]);
                    }
            }
            #pragma unroll
            for (int c = 0; c < 2; c++){
                float cnt = (float)s_count[2*w + c];
                if (cnt > 0.f)
                    #pragma unroll
                    for (int j = 0; j < 4; j++){
                        float g = 0.f;
                        #pragma unroll
                        for (int f = 0; f < 4; f++)
                            g += lrelu(f2red(b[c][f][j]) + s_b2[d4 + j]);
                        s_feat[(2*w+c)*ND + d4 + j] += cnt * g;
                    }
            }
        }
    }
    __syncthreads();
    load_f(s_b1, i2i_b1, ND);
    load_f(s_b2, i2i_b2, ND);
    __syncthreads();

    // ===== Phase 4: inter_items with message cache =====
    {
        const u64* W1 = g_w + GW_I2I1;
        const u64* W2 = g_w + GW_I2I2;
        float* s_hh  = s_scr;          // 16x128
        float* s_msg = s_scr + 2048;   // 16x128
        float* s_pt  = s_scr + 4096;   // 8x128
        float* s_y   = s_scr + 5120;   // 128
        {
            const int i0 = 2*w, i1 = 2*w + 1;
            if (s_count[i0] > 0 || s_count[i1] > 0){
                u64 a[2][4];
                #pragma unroll
                for (int c = 0; c < 2; c++)
                    #pragma unroll
                    for (int j = 0; j < 4; j++) a[c][j] = 0;
                #pragma unroll 4
                for (int q = 0; q < 32; q++){
                    ulonglong2 wa0 = ldg2(&W1[(2*q)*ND + d4]),   wb0 = ldg2(&W1[(2*q)*ND + d4 + 2]);
                    ulonglong2 wa1 = ldg2(&W1[(2*q+1)*ND + d4]), wb1 = ldg2(&W1[(2*q+1)*ND + d4 + 2]);
                    ulonglong2 x0 = ld2f(&s_feat[i0*ND + 4*q]);
                    ulonglong2 x1 = ld2f(&s_feat[i1*ND + 4*q]);
                    a[0][0]=f2fma(x0.x,wa0.x,a[0][0]); a[0][0]=f2fma(x0.y,wa1.x,a[0][0]);
                    a[0][1]=f2fma(x0.x,wa0.y,a[0][1]); a[0][1]=f2fma(x0.y,wa1.y,a[0][1]);
                    a[0][2]=f2fma(x0.x,wb0.x,a[0][2]); a[0][2]=f2fma(x0.y,wb1.x,a[0][2]);
                    a[0][3]=f2fma(x0.x,wb0.y,a[0][3]); a[0][3]=f2fma(x0.y,wb1.y,a[0][3]);
                    a[1][0]=f2fma(x1.x,wa0.x,a[1][0]); a[1][0]=f2fma(x1.y,wa1.x,a[1][0]);
                    a[1][1]=f2fma(x1.x,wa0.y,a[1][1]); a[1][1]=f2fma(x1.y,wa1.y,a[1][1]);
                    a[1][2]=f2fma(x1.x,wb0.x,a[1][2]); a[1][2]=f2fma(x1.y,wb1.x,a[1][2]);
                    a[1][3]=f2fma(x1.x,wb0.y,a[1][3]); a[1][3]=f2fma(x1.y,wb1.y,a[1][3]);
                }
                #pragma unroll
                for (int c = 0; c < 2; c++)
                    #pragma unroll
                    for (int j = 0; j < 4; j++)
                        s_hh[(2*w+c)*ND + d4 + j] = lrelu(f2red(a[c][j]) + s_b1[d4 + j]);
                __syncwarp();
                u64 b[2][4];
                #pragma unroll
                for (int c = 0; c < 2; c++)
                    #pragma unroll
                    for (int j = 0; j < 4; j++) b[c][j] = 0;
                #pragma unroll 4
                for (int q = 0; q < 32; q++){
                    ulonglong2 wa0 = ldg2(&W2[(2*q)*ND + d4]),   wb0 = ldg2(&W2[(2*q)*ND + d4 + 2]);
                    ulonglong2 wa1 = ldg2(&W2[(2*q+1)*ND + d4]), wb1 = ldg2(&W2[(2*q+1)*ND + d4 + 2]);
                    ulonglong2 x0 = ld2f(&s_hh[i0*ND + 4*q]);
                    ulonglong2 x1 = ld2f(&s_hh[i1*ND + 4*q]);
                    b[0][0]=f2fma(x0.x,wa0.x,b[0][0]); b[0][0]=f2fma(x0.y,wa1.x,b[0][0]);
                    b[0][1]=f2fma(x0.x,wa0.y,b[0][1]); b[0][1]=f2fma(x0.y,wa1.y,b[0][1]);
                    b[0][2]=f2fma(x0.x,wb0.x,b[0][2]); b[0][2]=f2fma(x0.y,wb1.x,b[0][2]);
                    b[0][3]=f2fma(x0.x,wb0.y,b[0][3]); b[0][3]=f2fma(x0.y,wb1.y,b[0][3]);
                    b[1][0]=f2fma(x1.x,wa0.x,b[1][0]); b[1][0]=f2fma(x1.y,wa1.x,b[1][0]);
                    b[1][1]=f2fma(x1.x,wa0.y,b[1][1]); b[1][1]=f2fma(x1.y,wa1.y,b[1][1]);
                    b[1][2]=f2fma(x1.x,wb0.x,b[1][2]); b[1][2]=f2fma(x1.y,wb1.x,b[1][2]);
                    b[1][3]=f2fma(x1.x,wb0.y,b[1][3]); b[1][3]=f2fma(x1.y,wb1.y,b[1][3]);
                }
                #pragma unroll
                for (int c = 0; c < 2; c++)
                    #pragma unroll
                    for (int j = 0; j < 4; j++)
                        s_msg[(2*w+c)*ND + d4 + j] = lrelu(f2red(b[c][j]) + s_b2[d4 + j]);
            }
            __syncthreads();
        }
        for (int step = 0; step < 8; step++){
            const int i = s_items[step];
            if (i < 0) continue;
            if (tid < ND){
                float s = s_feat[i*ND + tid];
                #pragma unroll
                for (int j = 0; j < 8; j++){
                    int it = s_items[j];
                    if (it != i) s += s_msg[it*ND + tid];
                }
                s_feat[i*ND + tid] = s;
            }
            __syncthreads();
            {
                u64 a[4] = {0,0,0,0};
                #pragma unroll
                for (int q = 0; q < 4; q++){
                    int kp = w*8 + 2*q;
                    ulonglong2 wa0 = ldg2(&W1[kp*ND + d4]),     wb0 = ldg2(&W1[kp*ND + d4 + 2]);
                    ulonglong2 wa1 = ldg2(&W1[(kp+1)*ND + d4]), wb1 = ldg2(&W1[(kp+1)*ND + d4 + 2]);
                    ulonglong2 x = ld2f(&s_feat[i*ND + w*16 + 4*q]);
                    a[0]=f2fma(x.x,wa0.x,a[0]); a[0]=f2fma(x.y,wa1.x,a[0]);
                    a[1]=f2fma(x.x,wa0.y,a[1]); a[1]=f2fma(x.y,wa1.y,a[1]);
                    a[2]=f2fma(x.x,wb0.x,a[2]); a[2]=f2fma(x.y,wb1.x,a[2]);
                    a[3]=f2fma(x.x,wb0.y,a[3]); a[3]=f2fma(x.y,wb1.y,a[3]);
                }
                #pragma unroll
                for (int j = 0; j < 4; j++) s_pt[w*ND + d4 + j] = f2red(a[j]);
            }
            __syncthreads();
            if (tid < ND){
                float s = s_b1[tid];
                #pragma unroll
                for (int pp = 0; pp < 8; pp++) s += s_pt[pp*ND + tid];
                s_y[tid] = lrelu(s);
            }
            __syncthreads();
            {
                u64 a[4] = {0,0,0,0};
                #pragma unroll
                for (int q = 0; q < 4; q++){
                    int kp = w*8 + 2*q;
                    ulonglong2 wa0 = ldg2(&W2[kp*ND + d4]),     wb0 = ldg2(&W2[kp*ND + d4 + 2]);
                    ulonglong2 wa1 = ldg2(&W2[(kp+1)*ND + d4]), wb1 = ldg2(&W2[(kp+1)*ND + d4 + 2]);
                    ulonglong2 x = ld2f(&s_y[w*16 + 4*q]);
                    a[0]=f2fma(x.x,wa0.x,a[0]); a[0]=f2fma(x.y,wa1.x,a[0]);
                    a[1]=f2fma(x.x,wa0.y,a[1]); a[1]=f2fma(x.y,wa1.y,a[1]);
                    a[2]=f2fma(x.x,wb0.x,a[2]); a[2]=f2fma(x.y,wb1.x,a[2]);
                    a[3]=f2fma(x.x,wb0.y,a[3]); a[3]=f2fma(x.y,wb1.y,a[3]);
                }
                #pragma unroll
                for (int j = 0; j < 4; j++) s_pt[w*ND + d4 + j] = f2red(a[j]);
            }
            __syncthreads();
            if (tid < ND){
                float s = s_b2[tid];
                #pragma unroll
                for (int pp = 0; pp < 8; pp++) s += s_pt[pp*ND + tid];
                s_msg[i*ND + tid] = lrelu(s);
            }
            __syncthreads();
        }
    }

    // ===== score + com finalize =====
    if (w == 0){
        float4 ov = make_float4(0.f,0.f,0.f,0.f);
        #pragma unroll
        for (int s = 0; s < 8; s++){
            int it = s_items[s];
            if (it >= 0){
                float4 fv = *(float4*)&s_feat[it*ND + lane*4];
                ov.x += fv.x; ov.y += fv.y; ov.z += fv.z; ov.w += fv.w;
            }
        }
        const float4 wv = *(const float4*)&o2s_W[lane*4];
        float pr = ov.x*wv.x + ov.y*wv.y + ov.z*wv.z + ov.w*wv.w;
        #pragma unroll
        for (int off2 = 16; off2; off2 >>= 1)
            pr += __shfl_xor_sync(0xffffffffu, pr, off2);
        if (lane == 0) d_out[o] = 1.f / (1.f + expf(-(pr + o2s_b[0])));
    }
    if (tid == 0){
        float tot = 0.f;
        #pragma unroll
        for (int ww = 0; ww < 8; ww++) tot += s_red[ww];
        g_com_partial[o] = tot;
        __threadfence();
        unsigned r = atomicAdd(&g_counter, 1u);
        *s_flag = (r == (unsigned)(NO - 1)) ? 1 : 0;
    }
    __syncthreads();
    if (*s_flag){
        __threadfence();
        float s = 0.f;
        #pragma unroll
        for (int c = 0; c < NO/NT; c++) s += g_com_partial[tid + c*NT];
        s_red[tid & 63] = 0.f;   // unused; keep region warm
        s_scr[tid] = s;
        __syncthreads();
        for (int st = NT/2; st > 0; st >>= 1){
            if (tid < st) s_scr[tid] += s_scr[tid + st];
            __syncthreads();
        }
        if (tid == 0){
            d_out[NO] = s_scr[0] / (float)NO;
            g_counter = 0;
        }
    }
}

extern "C" void kernel_launch(void* const* d_in, const int* in_sizes, int n_in,
                              void* d_out, int out_size)
{
    (void)in_sizes; (void)n_in; (void)out_size;
    static u64* gw_ptr = nullptr;
    if (!gw_ptr) cudaGetSymbolAddress((void**)&gw_ptr, g_w);
    cudaFuncSetAttribute(mfgn_kernel, cudaFuncAttributeMaxDynamicSharedMemorySize, SMEM_BYTES);

    pack_all<<<320, 256>>>(
        (const float*)d_in[4],  (const float*)d_in[6],
        (const float*)d_in[8],  (const float*)d_in[10],
        (const float*)d_in[12], (const float*)d_in[14],
        (const float*)d_in[16], (const float*)d_in[18], gw_ptr);

    mfgn_kernel<<<NO, NT, SMEM_BYTES>>>(
        (const int*)d_in[0], (const float*)d_in[1], (const int*)d_in[2],
        (const float*)d_in[5], (const float*)d_in[7],
        (const float*)d_in[9], (const float*)d_in[11],
        (const float*)d_in[13], (const float*)d_in[15],
        (const float*)d_in[17], (const float*)d_in[19],
        (const float*)d_in[20], (const float*)d_in[21], (float*)d_out);
}

// round 13
// speedup vs baseline: 1.8701x; 1.8701x over previous
#include <cuda_runtime.h>
#include <math.h>

#define NO 2048
#define NI 16
#define NF 4
#define ND 128
#define NN 8
#define NT 256

typedef unsigned long long u64;

// smem floats
#define OFF_FAC  0        // 8192
#define OFF_FEAT 8192     // 2048
#define OFF_H    10240    // 8192 (h rows; ctr aliased; ph4 scratch)
#define OFF_B1   18432
#define OFF_B2   18560
#define OFF_RED  18688    // 256
#define OFF_INT  18944    // 512 ints
#define SMEM_BYTES ((18944 + 512)*4)   // 77824 -> 2 CTAs/SM, L1D ~76KB

#define GW_CF1 0
#define GW_CF2 16384
#define GW_F2F1 32768
#define GW_F2F2 40960
#define GW_F2I1 49152
#define GW_F2I2 57344
#define GW_I2I1 65536
#define GW_I2I2 73728
__device__ u64 g_w[81920];
__device__ float g_com_partial[NO];
__device__ unsigned g_counter = 0;

__device__ __forceinline__ float lrelu(float v){ return v >= 0.f ? v : 0.01f*v; }
__device__ __forceinline__ u64 packff(float lo, float hi){
    u64 d; asm("mov.b64 %0, {%1, %2};" : "=l"(d) : "f"(lo), "f"(hi)); return d; }
__device__ __forceinline__ u64 f2fma(u64 a, u64 b, u64 c){
    u64 d; asm("fma.rn.f32x2 %0, %1, %2, %3;" : "=l"(d) : "l"(a), "l"(b), "l"(c)); return d; }
__device__ __forceinline__ u64 f2mul(u64 a, u64 b){
    u64 d; asm("mul.rn.f32x2 %0, %1, %2;" : "=l"(d) : "l"(a), "l"(b)); return d; }
__device__ __forceinline__ float f2red(u64 v){
    float lo, hi; asm("mov.b64 {%0, %1}, %2;" : "=f"(lo), "=f"(hi) : "l"(v)); return lo + hi; }
__device__ __forceinline__ ulonglong2 ld2f(const float* pf){ return *(const ulonglong2*)pf; }
__device__ __forceinline__ ulonglong2 ldg2(const u64* p){
    ulonglong2 r;
    asm("ld.global.nc.v2.u64 {%0, %1}, [%2];" : "=l"(r.x), "=l"(r.y) : "l"(p));
    return r;
}
__device__ __forceinline__ u64 ldg1(const u64* p){
    u64 r; asm("ld.global.nc.u64 %0, [%1];" : "=l"(r) : "l"(p)); return r;
}

__global__ void pack_all(const float* __restrict__ s0, const float* __restrict__ s1,
                         const float* __restrict__ s2, const float* __restrict__ s3,
                         const float* __restrict__ s4, const float* __restrict__ s5,
                         const float* __restrict__ s6, const float* __restrict__ s7,
                         u64* __restrict__ dst){
    int idx = blockIdx.x*256 + threadIdx.x;
    if (idx >= 81920) return;
    const float* src; int base, cshift;
    if (idx < 16384){ src = s0; base = 0; cshift = 6; }
    else if (idx < 32768){ src = s1; base = 16384; cshift = 7; }
    else {
        int t = (idx - 32768) >> 13;
        src = (t==0)?s2:(t==1)?s3:(t==2)?s4:(t==3)?s5:(t==4)?s6:s7;
        base = 32768 + t*8192; cshift = 7;
    }
    int l = idx - base;
    int k2 = l >> cshift, d = l & ((1 << cshift) - 1);
    dst[idx] = packff(src[((2*k2) << cshift) + d], src[((2*k2+1) << cshift) + d]);
}

__device__ __forceinline__ void load_f(float* dst, const float* src, int n){
    for (int i = threadIdx.x; i < n; i += NT) dst[i] = src[i];
}

__global__ __launch_bounds__(NT, 2)
void mfgn_kernel(
    const int* __restrict__ outfit_items, const float* __restrict__ items_feature,
    const int* __restrict__ items_neighbor,
    const float* __restrict__ cf_b1, const float* __restrict__ cf_b2,
    const float* __restrict__ f2f_b1, const float* __restrict__ f2f_b2,
    const float* __restrict__ f2i_b1, const float* __restrict__ f2i_b2,
    const float* __restrict__ i2i_b1, const float* __restrict__ i2i_b2,
    const float* __restrict__ o2s_W,  const float* __restrict__ o2s_b,
    float* __restrict__ d_out)
{
    extern __shared__ float sm[];
    float* s_fac  = sm + OFF_FAC;
    float* s_feat = sm + OFF_FEAT;
    float* s_h    = sm + OFF_H;
    float* s_b1   = sm + OFF_B1;
    float* s_b2   = sm + OFF_B2;
    float* s_red  = sm + OFF_RED;
    int*   s_items = (int*)(sm + OFF_INT);
    int*   s_nbr   = s_items + NI;
    int*   s_count = s_nbr + NI*NN;
    int*   s_cand  = s_count + NI;            // [8][16]
    float* s_cmask = (float*)(s_cand + 128);  // [8][16]
    int*   s_flag  = (int*)(s_cmask + 128);

    const int o = blockIdx.x, tid = threadIdx.x;
    const int w = tid >> 5, lane = tid & 31;
    const int d4 = lane*4;

    if (tid < NI)    s_items[tid] = outfit_items[o*NI + tid];
    if (tid < NI*NN) s_nbr[tid]   = items_neighbor[o*NI*NN + tid];
    load_f(s_feat, items_feature + (size_t)o*NI*ND, NI*ND);
    __syncthreads();
    if (tid < NI){
        int c = 0;
        #pragma unroll
        for (int s = 0; s < 8; s++) c += (s_items[s] == tid);
        s_count[tid] = c;
    }
    {   // dedup'd candidates with multiplicity; warp w -> step w
        const int i = s_items[w];
        int c = -1; bool v = false;
        if (i >= 0 && lane < NI + NN){
            c = (lane < NI) ? s_items[lane] : s_nbr[i*NN + (lane - NI)];
            v = (c != -1) && (c != i);
        }
        unsigned vb = __ballot_sync(0xffffffffu, v);
        unsigned mt = __match_any_sync(0xffffffffu, c) & vb;
        bool leader = v && ((mt & (0u - mt)) == (1u << lane));
        unsigned lb = __ballot_sync(0xffffffffu, leader);
        if (lane < 16){ s_cand[w*16 + lane] = 0; s_cmask[w*16 + lane] = 0.f; }
        __syncwarp();
        if (leader){
            int pos = __popc(lb & ((1u << lane) - 1));
            s_cand[w*16 + pos] = c;
            s_cmask[w*16 + pos] = (float)__popc(mt);
        }
    }

    // ===== Phase 1: creat_factors. warp w: items 2w,2w+1; loop f =====
    {
        const int i0 = 2*w, i1 = 2*w + 1;
        for (int f = 0; f < NF; f++){
            const u64* W1 = g_w + GW_CF1 + f*4096;
            const u64* W2 = g_w + GW_CF2 + f*4096;
            u64 a[2][2] = {{0,0},{0,0}};
            #pragma unroll 4
            for (int q = 0; q < 32; q++){
                u64 w0 = ldg1(&W1[(2*q)*64 + lane*2]),   w0b = ldg1(&W1[(2*q)*64 + lane*2 + 1]);
                u64 w1 = ldg1(&W1[(2*q+1)*64 + lane*2]), w1b = ldg1(&W1[(2*q+1)*64 + lane*2 + 1]);
                ulonglong2 x0 = ld2f(&s_feat[i0*ND + 4*q]);
                ulonglong2 x1 = ld2f(&s_feat[i1*ND + 4*q]);
                a[0][0]=f2fma(x0.x,w0,a[0][0]);  a[0][0]=f2fma(x0.y,w1,a[0][0]);
                a[0][1]=f2fma(x0.x,w0b,a[0][1]); a[0][1]=f2fma(x0.y,w1b,a[0][1]);
                a[1][0]=f2fma(x1.x,w0,a[1][0]);  a[1][0]=f2fma(x1.y,w1,a[1][0]);
                a[1][1]=f2fma(x1.x,w0b,a[1][1]); a[1][1]=f2fma(x1.y,w1b,a[1][1]);
            }
            float b10 = cf_b1[f*64 + lane*2], b11 = cf_b1[f*64 + lane*2 + 1];
            s_h[(w*2+0)*64 + lane*2+0] = lrelu(f2red(a[0][0]) + b10);
            s_h[(w*2+0)*64 + lane*2+1] = lrelu(f2red(a[0][1]) + b11);
            s_h[(w*2+1)*64 + lane*2+0] = lrelu(f2red(a[1][0]) + b10);
            s_h[(w*2+1)*64 + lane*2+1] = lrelu(f2red(a[1][1]) + b11);
            __syncwarp();
            u64 c2[2][4] = {{0,0,0,0},{0,0,0,0}};
            #pragma unroll 4
            for (int q = 0; q < 16; q++){
                ulonglong2 wa0 = ldg2(&W2[(2*q)*ND + d4]),   wb0 = ldg2(&W2[(2*q)*ND + d4 + 2]);
                ulonglong2 wa1 = ldg2(&W2[(2*q+1)*ND + d4]), wb1 = ldg2(&W2[(2*q+1)*ND + d4 + 2]);
                ulonglong2 h0 = ld2f(&s_h[(w*2+0)*64 + 4*q]);
                ulonglong2 h1 = ld2f(&s_h[(w*2+1)*64 + 4*q]);
                c2[0][0]=f2fma(h0.x,wa0.x,c2[0][0]); c2[0][0]=f2fma(h0.y,wa1.x,c2[0][0]);
                c2[0][1]=f2fma(h0.x,wa0.y,c2[0][1]); c2[0][1]=f2fma(h0.y,wa1.y,c2[0][1]);
                c2[0][2]=f2fma(h0.x,wb0.x,c2[0][2]); c2[0][2]=f2fma(h0.y,wb1.x,c2[0][2]);
                c2[0][3]=f2fma(h0.x,wb0.y,c2[0][3]); c2[0][3]=f2fma(h0.y,wb1.y,c2[0][3]);
                c2[1][0]=f2fma(h1.x,wa0.x,c2[1][0]); c2[1][0]=f2fma(h1.y,wa1.x,c2[1][0]);
                c2[1][1]=f2fma(h1.x,wa0.y,c2[1][1]); c2[1][1]=f2fma(h1.y,wa1.y,c2[1][1]);
                c2[1][2]=f2fma(h1.x,wb0.x,c2[1][2]); c2[1][2]=f2fma(h1.y,wb1.x,c2[1][2]);
                c2[1][3]=f2fma(h1.x,wb0.y,c2[1][3]); c2[1][3]=f2fma(h1.y,wb1.y,c2[1][3]);
            }
            #pragma unroll
            for (int r = 0; r < 2; r++)
                #pragma unroll
                for (int j = 0; j < 4; j++)
                    s_fac[(2*w+r)*512 + f*ND + d4 + j] =
                        lrelu(f2red(c2[r][j]) + cf_b2[f*ND + d4 + j]);
            __syncwarp();
        }
    }
    __syncthreads();
    load_f(s_b1, f2f_b1, ND);
    load_f(s_b2, f2f_b2, ND);
    __syncthreads();

    // ===== Phase 2: inter_factors. ctr aliased into first 512 of warp's h block =====
    {
        const u64* W1 = g_w + GW_F2F1;
        const u64* W2 = g_w + GW_F2F2;
        for (int step = 0; step < 8; step++){
            const int i = s_items[step];
            if (i < 0) continue;
            const float m0 = s_cmask[step*16 + 2*w], m1 = s_cmask[step*16 + 2*w + 1];
            if (m0 != 0.f){
                const int c0 = s_cand[step*16 + 2*w], c1 = s_cand[step*16 + 2*w + 1];
                const float* tb = s_fac + i*512;
                const float* e0 = s_fac + c0*512;
                const float* e1 = s_fac + c1*512;
                u64 a[2][4][4];
                #pragma unroll
                for (int c = 0; c < 2; c++)
                    #pragma unroll
                    for (int f = 0; f < 4; f++)
                        #pragma unroll
                        for (int j = 0; j < 4; j++) a[c][f][j] = 0;
                #pragma unroll 2
                for (int q = 0; q < 32; q++){
                    ulonglong2 wa0 = ldg2(&W1[(2*q)*ND + d4]),   wb0 = ldg2(&W1[(2*q)*ND + d4 + 2]);
                    ulonglong2 wa1 = ldg2(&W1[(2*q+1)*ND + d4]), wb1 = ldg2(&W1[(2*q+1)*ND + d4 + 2]);
                    #pragma unroll
                    for (int f = 0; f < 4; f++){
                        ulonglong2 t  = ld2f(&tb[f*ND + 4*q]);
                        ulonglong2 x0 = ld2f(&e0[f*ND + 4*q]);
                        ulonglong2 x1 = ld2f(&e1[f*ND + 4*q]);
                        u64 p0 = f2mul(t.x, x0.x), p1 = f2mul(t.y, x0.y);
                        a[0][f][0]=f2fma(p0,wa0.x,a[0][f][0]); a[0][f][0]=f2fma(p1,wa1.x,a[0][f][0]);
                        a[0][f][1]=f2fma(p0,wa0.y,a[0][f][1]); a[0][f][1]=f2fma(p1,wa1.y,a[0][f][1]);
                        a[0][f][2]=f2fma(p0,wb0.x,a[0][f][2]); a[0][f][2]=f2fma(p1,wb1.x,a[0][f][2]);
                        a[0][f][3]=f2fma(p0,wb0.y,a[0][f][3]); a[0][f][3]=f2fma(p1,wb1.y,a[0][f][3]);
                        u64 r0 = f2mul(t.x, x1.x), r1 = f2mul(t.y, x1.y);
                        a[1][f][0]=f2fma(r0,wa0.x,a[1][f][0]); a[1][f][0]=f2fma(r1,wa1.x,a[1][f][0]);
                        a[1][f][1]=f2fma(r0,wa0.y,a[1][f][1]); a[1][f][1]=f2fma(r1,wa1.y,a[1][f][1]);
                        a[1][f][2]=f2fma(r0,wb0.x,a[1][f][2]); a[1][f][2]=f2fma(r1,wb1.x,a[1][f][2]);
                        a[1][f][3]=f2fma(r0,wb0.y,a[1][f][3]); a[1][f][3]=f2fma(r1,wb1.y,a[1][f][3]);
                    }
                }
                #pragma unroll
                for (int c = 0; c < 2; c++)
                    #pragma unroll
                    for (int f = 0; f < 4; f++)
                        #pragma unroll
                        for (int j = 0; j < 4; j++)
                            s_h[w*1024 + (c*4+f)*ND + d4 + j] =
                                lrelu(f2red(a[c][f][j]) + s_b1[d4 + j]);
                __syncwarp();
                u64 b[2][4][4];
                #pragma unroll
                for (int c = 0; c < 2; c++)
                    #pragma unroll
                    for (int f = 0; f < 4; f++)
                        #pragma unroll
                        for (int j = 0; j < 4; j++) b[c][f][j] = 0;
                #pragma unroll 2
                for (int q = 0; q < 32; q++){
                    ulonglong2 wa0 = ldg2(&W2[(2*q)*ND + d4]),   wb0 = ldg2(&W2[(2*q)*ND + d4 + 2]);
                    ulonglong2 wa1 = ldg2(&W2[(2*q+1)*ND + d4]), wb1 = ldg2(&W2[(2*q+1)*ND + d4 + 2]);
                    #pragma unroll
                    for (int c = 0; c < 2; c++)
                        #pragma unroll
                        for (int f = 0; f < 4; f++){
                            ulonglong2 h4 = ld2f(&s_h[w*1024 + (c*4+f)*ND + 4*q]);
                            b[c][f][0]=f2fma(h4.x,wa0.x,b[c][f][0]); b[c][f][0]=f2fma(h4.y,wa1.x,b[c][f][0]);
                            b[c][f][1]=f2fma(h4.x,wa0.y,b[c][f][1]); b[c][f][1]=f2fma(h4.y,wa1.y,b[c][f][1]);
                            b[c][f][2]=f2fma(h4.x,wb0.x,b[c][f][2]); b[c][f][2]=f2fma(h4.y,wb1.x,b[c][f][2]);
                            b[c][f][3]=f2fma(h4.x,wb0.y,b[c][f][3]); b[c][f][3]=f2fma(h4.y,wb1.y,b[c][f][3]);
                        }
                }
                __syncwarp();   // all lanes done reading h before ctr overwrite
                #pragma unroll
                for (int f = 0; f < 4; f++)
                    #pragma unroll
                    for (int j = 0; j < 4; j++){
                        float y0 = lrelu(f2red(b[0][f][j]) + s_b2[d4 + j]);
                        float y1 = lrelu(f2red(b[1][f][j]) + s_b2[d4 + j]);
                        s_h[w*1024 + f*ND + d4 + j] = m0*y0 + m1*y1;
                    }
            } else {
                #pragma unroll
                for (int f = 0; f < 4; f++)
                    #pragma unroll
                    for (int j = 0; j < 4; j++)
                        s_h[w*1024 + f*ND + d4 + j] = 0.f;
            }
            __syncthreads();
            #pragma unroll
            for (int rep = 0; rep < 2; rep++){
                int idx = tid + rep*256;
                float s = 0.f;
                #pragma unroll
                for (int pp = 0; pp < 8; pp++) s += s_h[pp*1024 + idx];
                s_fac[i*512 + idx] += s;
            }
            __syncthreads();
        }
    }

    // ===== com partial: warp w -> positions 2w, 2w+1 =====
    {
        float csum = 0.f;
        #pragma unroll
        for (int t2 = 0; t2 < 2; t2++){
            int pos = 2*w + t2;
            if (s_items[pos] != -1){
                const float* fp = s_fac + pos*512;
                #pragma unroll
                for (int aa = 0; aa < NF; aa++)
                    #pragma unroll
                    for (int bb = 0; bb < NF; bb++){
                        float pr = 0.f;
                        #pragma unroll
                        for (int k = 0; k < 4; k++)
                            pr += fp[aa*ND + lane + 32*k] * fp[bb*ND + lane + 32*k];
                        #pragma unroll
                        for (int off2 = 16; off2; off2 >>= 1)
                            pr += __shfl_xor_sync(0xffffffffu, pr, off2);
                        float gg = pr - (aa == bb ? 1.f : 0.f);
                        csum += gg*gg;
                    }
            }
        }
        if (lane == 0) s_red[w] = csum;
    }
    __syncthreads();
    load_f(s_b1, f2i_b1, ND);
    load_f(s_b2, f2i_b2, ND);
    __syncthreads();

    // ===== Phase 3: infer_items. warp w: items 2w,2w+1 =====
    {
        const u64* W1 = g_w + GW_F2I1;
        const u64* W2 = g_w + GW_F2I2;
        const int cn0 = s_count[2*w], cn1 = s_count[2*w+1];
        if (cn0 > 0 || cn1 > 0){
            u64 a[2][4][4];
            #pragma unroll
            for (int c = 0; c < 2; c++)
                #pragma unroll
                for (int f = 0; f < 4; f++)
                    #pragma unroll
                    for (int j = 0; j < 4; j++) a[c][f][j] = 0;
            #pragma unroll 2
            for (int q = 0; q < 32; q++){
                ulonglong2 wa0 = ldg2(&W1[(2*q)*ND + d4]),   wb0 = ldg2(&W1[(2*q)*ND + d4 + 2]);
                ulonglong2 wa1 = ldg2(&W1[(2*q+1)*ND + d4]), wb1 = ldg2(&W1[(2*q+1)*ND + d4 + 2]);
                #pragma unroll
                for (int c = 0; c < 2; c++)
                    #pragma unroll
                    for (int f = 0; f < 4; f++){
                        ulonglong2 x = ld2f(&s_fac[(2*w+c)*512 + f*ND + 4*q]);
                        a[c][f][0]=f2fma(x.x,wa0.x,a[c][f][0]); a[c][f][0]=f2fma(x.y,wa1.x,a[c][f][0]);
                        a[c][f][1]=f2fma(x.x,wa0.y,a[c][f][1]); a[c][f][1]=f2fma(x.y,wa1.y,a[c][f][1]);
                        a[c][f][2]=f2fma(x.x,wb0.x,a[c][f][2]); a[c][f][2]=f2fma(x.y,wb1.x,a[c][f][2]);
                        a[c][f][3]=f2fma(x.x,wb0.y,a[c][f][3]); a[c][f][3]=f2fma(x.y,wb1.y,a[c][f][3]);
                    }
            }
            #pragma unroll
            for (int c = 0; c < 2; c++)
                #pragma unroll
                for (int f = 0; f < 4; f++)
                    #pragma unroll
                    for (int j = 0; j < 4; j++)
                        s_h[w*1024 + (c*4+f)*ND + d4 + j] =
                            lrelu(f2red(a[c][f][j]) + s_b1[d4 + j]);
            __syncwarp();
            u64 b[2][4][4];
            #pragma unroll
            for (int c = 0; c < 2; c++)
                #pragma unroll
                for (int f = 0; f < 4; f++)
                    #pragma unroll
                    for (int j = 0; j < 4; j++) b[c][f][j] = 0;
            #pragma unroll 2
            for (int q = 0; q < 32; q++){
                ulonglong2 wa0 = ldg2(&W2[(2*q)*ND + d4]),   wb0 = ldg2(&W2[(2*q)*ND + d4 + 2]);
                ulonglong2 wa1 = ldg2(&W2[(2*q+1)*ND + d4]), wb1 = ldg2(&W2[(2*q+1)*ND + d4 + 2]);
                #pragma unroll
                for (int c = 0; c < 2; c++)
                    #pragma unroll
                    for (int f = 0; f < 4; f++){
                        ulonglong2 h4 = ld2f(&s_h[w*1024 + (c*4+f)*ND + 4*q]);
                        b[c][f][0]=f2fma(h4.x,wa0.x,b[c][f][0]); b[c][f][0]=f2fma(h4.y,wa1.x,b[c][f][0]);
                        b[c][f][1]=f2fma(h4.x,wa0.y,b[c][f][1]); b[c][f][1]=f2fma(h4.y,wa1.y,b[c][f][1]);
                        b[c][f][2]=f2fma(h4.x,wb0.x,b[c][f][2]); b[c][f][2]=f2fma(h4.y,wb1.x,b[c][f][2]);
                        b[c][f][3]=f2fma(h4.x,wb0.y,b[c][f][3]); b[c][f][3]=f2fma(h4.y,wb1.y,b[c][f][3]);
                    }
            }
            #pragma unroll
            for (int c = 0; c < 2; c++){
                float cnt = (float)s_count[2*w + c];
                if (cnt > 0.f)
                    #pragma unroll
                    for (int j = 0; j < 4; j++){
                        float g = 0.f;
                        #pragma unroll
                        for (int f = 0; f < 4; f++)
                            g += lrelu(f2red(b[c][f][j]) + s_b2[d4 + j]);
                        s_feat[(2*w+c)*ND + d4 + j] += cnt * g;
                    }
            }
        }
    }
    __syncthreads();
    load_f(s_b1, i2i_b1, ND);
    load_f(s_b2, i2i_b2, ND);
    __syncthreads();

    // ===== Phase 4: inter_items with message cache =====
    {
        const u64* W1 = g_w + GW_I2I1;
        const u64* W2 = g_w + GW_I2I2;
        float* s_hh  = s_h;          // 16x128
        float* s_msg = s_h + 2048;   // 16x128
        float* s_pt  = s_h + 4096;   // 8x128
        float* s_y   = s_h + 5120;   // 128
        {
            const int i0 = 2*w, i1 = 2*w + 1;
            if (s_count[i0] > 0 || s_count[i1] > 0){
                u64 a[2][4];
                #pragma unroll
                for (int c = 0; c < 2; c++)
                    #pragma unroll
                    for (int j = 0; j < 4; j++) a[c][j] = 0;
                #pragma unroll 4
                for (int q = 0; q < 32; q++){
                    ulonglong2 wa0 = ldg2(&W1[(2*q)*ND + d4]),   wb0 = ldg2(&W1[(2*q)*ND + d4 + 2]);
                    ulonglong2 wa1 = ldg2(&W1[(2*q+1)*ND + d4]), wb1 = ldg2(&W1[(2*q+1)*ND + d4 + 2]);
                    ulonglong2 x0 = ld2f(&s_feat[i0*ND + 4*q]);
                    ulonglong2 x1 = ld2f(&s_feat[i1*ND + 4*q]);
                    a[0][0]=f2fma(x0.x,wa0.x,a[0][0]); a[0][0]=f2fma(x0.y,wa1.x,a[0][0]);
                    a[0][1]=f2fma(x0.x,wa0.y,a[0][1]); a[0][1]=f2fma(x0.y,wa1.y,a[0][1]);
                    a[0][2]=f2fma(x0.x,wb0.x,a[0][2]); a[0][2]=f2fma(x0.y,wb1.x,a[0][2]);
                    a[0][3]=f2fma(x0.x,wb0.y,a[0][3]); a[0][3]=f2fma(x0.y,wb1.y,a[0][3]);
                    a[1][0]=f2fma(x1.x,wa0.x,a[1][0]); a[1][0]=f2fma(x1.y,wa1.x,a[1][0]);
                    a[1][1]=f2fma(x1.x,wa0.y,a[1][1]); a[1][1]=f2fma(x1.y,wa1.y,a[1][1]);
                    a[1][2]=f2fma(x1.x,wb0.x,a[1][2]); a[1][2]=f2fma(x1.y,wb1.x,a[1][2]);
                    a[1][3]=f2fma(x1.x,wb0.y,a[1][3]); a[1][3]=f2fma(x1.y,wb1.y,a[1][3]);
                }
                #pragma unroll
                for (int c = 0; c < 2; c++)
                    #pragma unroll
                    for (int j = 0; j < 4; j++)
                        s_hh[(2*w+c)*ND + d4 + j] = lrelu(f2red(a[c][j]) + s_b1[d4 + j]);
                __syncwarp();
                u64 b[2][4];
                #pragma unroll
                for (int c = 0; c < 2; c++)
                    #pragma unroll
                    for (int j = 0; j < 4; j++) b[c][j] = 0;
                #pragma unroll 4
                for (int q = 0; q < 32; q++){
                    ulonglong2 wa0 = ldg2(&W2[(2*q)*ND + d4]),   wb0 = ldg2(&W2[(2*q)*ND + d4 + 2]);
                    ulonglong2 wa1 = ldg2(&W2[(2*q+1)*ND + d4]), wb1 = ldg2(&W2[(2*q+1)*ND + d4 + 2]);
                    ulonglong2 x0 = ld2f(&s_hh[i0*ND + 4*q]);
                    ulonglong2 x1 = ld2f(&s_hh[i1*ND + 4*q]);
                    b[0][0]=f2fma(x0.x,wa0.x,b[0][0]); b[0][0]=f2fma(x0.y,wa1.x,b[0][0]);
                    b[0][1]=f2fma(x0.x,wa0.y,b[0][1]); b[0][1]=f2fma(x0.y,wa1.y,b[0][1]);
                    b[0][2]=f2fma(x0.x,wb0.x,b[0][2]); b[0][2]=f2fma(x0.y,wb1.x,b[0][2]);
                    b[0][3]=f2fma(x0.x,wb0.y,b[0][3]); b[0][3]=f2fma(x0.y,wb1.y,b[0][3]);
                    b[1][0]=f2fma(x1.x,wa0.x,b[1][0]); b[1][0]=f2fma(x1.y,wa1.x,b[1][0]);
                    b[1][1]=f2fma(x1.x,wa0.y,b[1][1]); b[1][1]=f2fma(x1.y,wa1.y,b[1][1]);
                    b[1][2]=f2fma(x1.x,wb0.x,b[1][2]); b[1][2]=f2fma(x1.y,wb1.x,b[1][2]);
                    b[1][3]=f2fma(x1.x,wb0.y,b[1][3]); b[1][3]=f2fma(x1.y,wb1.y,b[1][3]);
                }
                #pragma unroll
                for (int c = 0; c < 2; c++)
                    #pragma unroll
                    for (int j = 0; j < 4; j++)
                        s_msg[(2*w+c)*ND + d4 + j] = lrelu(f2red(b[c][j]) + s_b2[d4 + j]);
            }
            __syncthreads();
        }
        for (int step = 0; step < 8; step++){
            const int i = s_items[step];
            if (i < 0) continue;
            if (tid < ND){
                float s = s_feat[i*ND + tid];
                #pragma unroll
                for (int j = 0; j < 8; j++){
                    int it = s_items[j];
                    if (it != i) s += s_msg[it*ND + tid];
                }
                s_feat[i*ND + tid] = s;
            }
            __syncthreads();
            {
                u64 a[4] = {0,0,0,0};
                #pragma unroll
                for (int q = 0; q < 4; q++){
                    int kp = w*8 + 2*q;
                    ulonglong2 wa0 = ldg2(&W1[kp*ND + d4]),     wb0 = ldg2(&W1[kp*ND + d4 + 2]);
                    ulonglong2 wa1 = ldg2(&W1[(kp+1)*ND + d4]), wb1 = ldg2(&W1[(kp+1)*ND + d4 + 2]);
                    ulonglong2 x = ld2f(&s_feat[i*ND + w*16 + 4*q]);
                    a[0]=f2fma(x.x,wa0.x,a[0]); a[0]=f2fma(x.y,wa1.x,a[0]);
                    a[1]=f2fma(x.x,wa0.y,a[1]); a[1]=f2fma(x.y,wa1.y,a[1]);
                    a[2]=f2fma(x.x,wb0.x,a[2]); a[2]=f2fma(x.y,wb1.x,a[2]);
                    a[3]=f2fma(x.x,wb0.y,a[3]); a[3]=f2fma(x.y,wb1.y,a[3]);
                }
                #pragma unroll
                for (int j = 0; j < 4; j++) s_pt[w*ND + d4 + j] = f2red(a[j]);
            }
            __syncthreads();
            if (tid < ND){
                float s = s_b1[tid];
                #pragma unroll
                for (int pp = 0; pp < 8; pp++) s += s_pt[pp*ND + tid];
                s_y[tid] = lrelu(s);
            }
            __syncthreads();
            {
                u64 a[4] = {0,0,0,0};
                #pragma unroll
                for (int q = 0; q < 4; q++){
                    int kp = w*8 + 2*q;
                    ulonglong2 wa0 = ldg2(&W2[kp*ND + d4]),     wb0 = ldg2(&W2[kp*ND + d4 + 2]);
                    ulonglong2 wa1 = ldg2(&W2[(kp+1)*ND + d4]), wb1 = ldg2(&W2[(kp+1)*ND + d4 + 2]);
                    ulonglong2 x = ld2f(&s_y[w*16 + 4*q]);
                    a[0]=f2fma(x.x,wa0.x,a[0]); a[0]=f2fma(x.y,wa1.x,a[0]);
                    a[1]=f2fma(x.x,wa0.y,a[1]); a[1]=f2fma(x.y,wa1.y,a[1]);
                    a[2]=f2fma(x.x,wb0.x,a[2]); a[2]=f2fma(x.y,wb1.x,a[2]);
                    a[3]=f2fma(x.x,wb0.y,a[3]); a[3]=f2fma(x.y,wb1.y,a[3]);
                }
                #pragma unroll
                for (int j = 0; j < 4; j++) s_pt[w*ND + d4 + j] = f2red(a[j]);
            }
            __syncthreads();
            if (tid < ND){
                float s = s_b2[tid];
                #pragma unroll
                for (int pp = 0; pp < 8; pp++) s += s_pt[pp*ND + tid];
                s_msg[i*ND + tid] = lrelu(s);
            }
            __syncthreads();
        }
    }

    // ===== score + com finalize =====
    if (w == 0){
        float4 ov = make_float4(0.f,0.f,0.f,0.f);
        #pragma unroll
        for (int s = 0; s < 8; s++){
            int it = s_items[s];
            if (it >= 0){
                float4 fv = *(float4*)&s_feat[it*ND + lane*4];
                ov.x += fv.x; ov.y += fv.y; ov.z += fv.z; ov.w += fv.w;
            }
        }
        const float4 wv = *(const float4*)&o2s_W[lane*4];
        float pr = ov.x*wv.x + ov.y*wv.y + ov.z*wv.z + ov.w*wv.w;
        #pragma unroll
        for (int off2 = 16; off2; off2 >>= 1)
            pr += __shfl_xor_sync(0xffffffffu, pr, off2);
        if (lane == 0) d_out[o] = 1.f / (1.f + expf(-(pr + o2s_b[0])));
    }
    if (tid == 0){
        float tot = 0.f;
        #pragma unroll
        for (int ww = 0; ww < 8; ww++) tot += s_red[ww];
        g_com_partial[o] = tot;
        __threadfence();
        unsigned r = atomicAdd(&g_counter, 1u);
        *s_flag = (r == (unsigned)(NO - 1)) ? 1 : 0;
    }
    __syncthreads();
    if (*s_flag){
        __threadfence();
        float s = 0.f;
        #pragma unroll
        for (int c = 0; c < NO/NT; c++) s += g_com_partial[tid + c*NT];
        s_red[tid] = s;
        __syncthreads();
        for (int st = NT/2; st > 0; st >>= 1){
            if (tid < st) s_red[tid] += s_red[tid + st];
            __syncthreads();
        }
        if (tid == 0){
            d_out[NO] = s_red[0] / (float)NO;
            g_counter = 0;
        }
    }
}

extern "C" void kernel_launch(void* const* d_in, const int* in_sizes, int n_in,
                              void* d_out, int out_size)
{
    (void)in_sizes; (void)n_in; (void)out_size;
    static u64* gw_ptr = nullptr;
    if (!gw_ptr) cudaGetSymbolAddress((void**)&gw_ptr, g_w);
    cudaFuncSetAttribute(mfgn_kernel, cudaFuncAttributeMaxDynamicSharedMemorySize, SMEM_BYTES);

    pack_all<<<320, 256>>>(
        (const float*)d_in[4],  (const float*)d_in[6],
        (const float*)d_in[8],  (const float*)d_in[10],
        (const float*)d_in[12], (const float*)d_in[14],
        (const float*)d_in[16], (const float*)d_in[18], gw_ptr);

    mfgn_kernel<<<NO, NT, SMEM_BYTES>>>(
        (const int*)d_in[0], (const float*)d_in[1], (const int*)d_in[2],
        (const float*)d_in[5], (const float*)d_in[7],
        (const float*)d_in[9], (const float*)d_in[11],
        (const float*)d_in[13], (const float*)d_in[15],
        (const float*)d_in[17], (const float*)d_in[19],
        (const float*)d_in[20], (const float*)d_in[21], (float*)d_out);
}